// round 5
// baseline (speedup 1.0000x reference)
#include <cuda_runtime.h>
#include <cuda_bf16.h>
#include <cstdint>

// Problem constants (fixed by the reference).
#define N_ENT   50000
#define N_REL   16
#define N_BASES 8
#define H_DIM   128
#define N_EDGES 800000
#define NT      391                     // ceil(N_ENT/128) src tiles
#define NBINS   (N_REL * NT)            // 6256

// ---------------------------------------------------------------------------
// Device scratch (allocation-free rule: __device__ globals).
// ---------------------------------------------------------------------------
__device__ __nv_bfloat16 g_Wt_hi[17 * H_DIM * H_DIM];   // [r][o][i]  (N,K) K-major
__device__ __nv_bfloat16 g_Wt_lo[17 * H_DIM * H_DIM];
__device__ __nv_bfloat16 g_A_hi[(size_t)N_ENT * H_DIM];
__device__ __nv_bfloat16 g_A_lo[(size_t)N_ENT * H_DIM];
__device__ float         g_H1[(size_t)N_ENT * H_DIM];
__device__ int           g_cnt[NBINS];
__device__ int           g_off[NBINS];
__device__ int           g_cur[NBINS];
__device__ uint32_t      g_perm[N_EDGES];   // (dst<<7) | (src&127)

// ---------------------------------------------------------------------------
// helpers
// ---------------------------------------------------------------------------
__device__ __forceinline__ uint32_t smem_u32(const void* p) {
    uint32_t a;
    asm("{ .reg .u64 t; cvta.to.shared.u64 t, %1; cvt.u32.u64 %0, t; }"
        : "=r"(a) : "l"(p));
    return a;
}

#define LDMX4(r0, r1, r2, r3, addr)                                           \
    asm volatile("ldmatrix.sync.aligned.m8n8.x4.shared.b16 {%0,%1,%2,%3}, [%4];" \
                 : "=r"(r0), "=r"(r1), "=r"(r2), "=r"(r3) : "r"(addr))

#define MMA_BF16(C, A, B)                                                     \
    asm volatile(                                                             \
        "mma.sync.aligned.m16n8k16.row.col.f32.bf16.bf16.f32 "                \
        "{%0,%1,%2,%3}, {%4,%5,%6,%7}, {%8,%9}, {%0,%1,%2,%3};"               \
        : "+f"((C)[0]), "+f"((C)[1]), "+f"((C)[2]), "+f"((C)[3])              \
        : "r"((A)[0]), "r"((A)[1]), "r"((A)[2]), "r"((A)[3]),                 \
          "r"((B)[0]), "r"((B)[1]))

#define RED_V4(ptr, v)                                                        \
    asm volatile("red.global.add.v4.f32 [%0], {%1,%2,%3,%4};"                 \
                 :: "l"(ptr), "f"((v).x), "f"((v).y), "f"((v).z), "f"((v).w)  \
                 : "memory")

// ---------------------------------------------------------------------------
// Edge binning: bin = rel*NT + (src>>7)
// ---------------------------------------------------------------------------
__global__ void zero_cnt_kernel(int* __restrict__ cnt)
{
    int i = blockIdx.x * blockDim.x + threadIdx.x;
    if (i < NBINS) cnt[i] = 0;
}

__global__ void hist_kernel(const int* __restrict__ src,
                            const int* __restrict__ rel,
                            int* __restrict__ cnt, int E)
{
    int e = blockIdx.x * blockDim.x + threadIdx.x;
    if (e >= E) return;
    atomicAdd(&cnt[rel[e] * NT + (src[e] >> 7)], 1);
}

__global__ __launch_bounds__(1024)
void scan_kernel(const int* __restrict__ cnt,
                 int* __restrict__ off, int* __restrict__ cur)
{
    __shared__ int ps[1024];
    const int t = threadIdx.x;
    const int CH = (NBINS + 1023) / 1024;    // 7
    int local[7];
    int s = 0;
#pragma unroll
    for (int i = 0; i < CH; i++) {
        int idx = t * CH + i;
        int v = (idx < NBINS) ? cnt[idx] : 0;
        local[i] = s;
        s += v;
    }
    ps[t] = s;
    __syncthreads();
    for (int d = 1; d < 1024; d <<= 1) {
        int v = (t >= d) ? ps[t - d] : 0;
        __syncthreads();
        ps[t] += v;
        __syncthreads();
    }
    int pre = ps[t] - s;                      // exclusive prefix of this chunk
#pragma unroll
    for (int i = 0; i < CH; i++) {
        int idx = t * CH + i;
        if (idx < NBINS) {
            int o = pre + local[i];
            off[idx] = o;
            cur[idx] = o;
        }
    }
}

__global__ void fill_kernel(const int* __restrict__ src,
                            const int* __restrict__ dst,
                            const int* __restrict__ rel,
                            int* __restrict__ cur,
                            uint32_t* __restrict__ perm, int E)
{
    int e = blockIdx.x * blockDim.x + threadIdx.x;
    if (e >= E) return;
    int s = src[e];
    int b = rel[e] * NT + (s >> 7);
    int pos = atomicAdd(&cur[b], 1);
    perm[pos] = ((uint32_t)dst[e] << 7) | (uint32_t)(s & 127);
}

// ---------------------------------------------------------------------------
// Combine bases -> transposed bf16 hi/lo weights.
// ---------------------------------------------------------------------------
__global__ void combine_bases_kernel(const float* __restrict__ basis,
                                     const float* __restrict__ w_comp,
                                     const float* __restrict__ loop_w,
                                     __nv_bfloat16* __restrict__ Wt_hi,
                                     __nv_bfloat16* __restrict__ Wt_lo)
{
    int idx = blockIdx.x * blockDim.x + threadIdx.x;
    const int total = 17 * H_DIM * H_DIM;
    if (idx >= total) return;
    int r  = idx >> 14;
    int io = idx & 16383;          // i*128 + o
    float s;
    if (r < N_REL) {
        s = 0.f;
#pragma unroll
        for (int b = 0; b < N_BASES; b++)
            s += w_comp[r * N_BASES + b] * basis[b * (H_DIM * H_DIM) + io];
    } else {
        s = loop_w[io];
    }
    int i = io >> 7, o = io & 127;
    size_t oidx = (size_t)r * 16384 + o * 128 + i;   // [r][o][i]
    __nv_bfloat16 hi = __float2bfloat16(s);
    __nv_bfloat16 lo = __float2bfloat16(s - __bfloat162float(hi));
    Wt_hi[oidx] = hi;
    Wt_lo[oidx] = lo;
}

// ---------------------------------------------------------------------------
// Split input activations fp32 -> bf16 hi/lo (optional fused ReLU).
// ---------------------------------------------------------------------------
__global__ void split_kernel(const float* __restrict__ x,
                             __nv_bfloat16* __restrict__ hi,
                             __nv_bfloat16* __restrict__ lo,
                             int n4, int relu)
{
    int i = blockIdx.x * blockDim.x + threadIdx.x;
    if (i >= n4) return;
    float4 v = ((const float4*)x)[i];
    if (relu) {
        v.x = fmaxf(v.x, 0.f); v.y = fmaxf(v.y, 0.f);
        v.z = fmaxf(v.z, 0.f); v.w = fmaxf(v.w, 0.f);
    }
    float e[4] = {v.x, v.y, v.z, v.w};
    __nv_bfloat16 h[4], l[4];
#pragma unroll
    for (int j = 0; j < 4; j++) {
        h[j] = __float2bfloat16(e[j]);
        l[j] = __float2bfloat16(e[j] - __bfloat162float(h[j]));
    }
    ((__nv_bfloat162*)hi)[2 * i]     = __nv_bfloat162(h[0], h[1]);
    ((__nv_bfloat162*)hi)[2 * i + 1] = __nv_bfloat162(h[2], h[3]);
    ((__nv_bfloat162*)lo)[2 * i]     = __nv_bfloat162(l[0], l[1]);
    ((__nv_bfloat162*)lo)[2 * i + 1] = __nv_bfloat162(l[2], l[3]);
}

// ---------------------------------------------------------------------------
// Initialize output with bias (atomic-add target must pre-exist).
// ---------------------------------------------------------------------------
__global__ void init_out_kernel(float* __restrict__ out,
                                const float* __restrict__ bias, int n)
{
    int i = blockIdx.x * blockDim.x + threadIdx.x;
    if (i >= n) return;
    out[i] = bias[i & (H_DIM - 1)];
}

// ---------------------------------------------------------------------------
// Fused GEMM + scatter.
//    Grid: (2 n-halves, NT m-tiles). CTA: 256 thr = 8 warps (4M x 2N),
//    warp tile 32x32, 3-term bf16 split. A tile resident across 17 r's.
//    Per r: MMA -> acc -> smem tile (overlays W region) -> scatter:
//      r <  16: edges of bin(r, mtile): out[dst] += tile[src&127]
//      r == 16: dense self-loop: out[m0+row] += tile[row]
// ---------------------------------------------------------------------------
#define PITCH   272                    // bf16 tile row pitch (bytes)
#define PITCHF  68                     // fp32 out-tile pitch (floats) = 272B
#define SM_A_HI 0
#define SM_A_LO 34816                  // 128*272
#define SM_W_HI 69632                  // 64*272 each; overlaid by out-tile
#define SM_W_LO 87040
#define GEMM_SMEM 104448               // 69632 + 34816 (= 128*68*4 out tile)

__global__ __launch_bounds__(256, 2)
void gemm_scatter_kernel(const __nv_bfloat16* __restrict__ Ahi,
                         const __nv_bfloat16* __restrict__ Alo,
                         const __nv_bfloat16* __restrict__ Wthi,
                         const __nv_bfloat16* __restrict__ Wtlo,
                         const int* __restrict__ boff,
                         const int* __restrict__ bcnt,
                         const uint32_t* __restrict__ perm,
                         float* __restrict__ OUT,
                         int M)
{
    extern __shared__ char smem[];
    const uint32_t sb = smem_u32(smem);
    float* stile = (float*)(smem + SM_W_HI);     // 128 x 68 fp32, overlays W
    const int tid   = threadIdx.x;
    const int wid   = tid >> 5;
    const int lane  = tid & 31;
    const int wm    = wid >> 1;             // 0..3
    const int wn    = wid & 1;              // 0..1
    const int nhalf = blockIdx.x;           // 0..1
    const int mtile = blockIdx.y;
    const int m0    = mtile * 128;

    // ---- load A tile (hi, lo): 128 rows x 128 bf16 each ----
#pragma unroll
    for (int t = 0; t < 2; t++) {
        const __nv_bfloat16* srcp = t ? Alo : Ahi;
        char* dstb = smem + (t ? SM_A_LO : SM_A_HI);
#pragma unroll
        for (int i = 0; i < 8; i++) {
            int idx = tid + i * 256;        // 0..2047
            int row = idx >> 4;
            int c   = idx & 15;
            uint4 v = make_uint4(0u, 0u, 0u, 0u);
            if (m0 + row < M)
                v = *(const uint4*)(srcp + (size_t)(m0 + row) * H_DIM + c * 8);
            *(uint4*)(dstb + row * PITCH + c * 16) = v;
        }
    }

    // ldmatrix per-lane address components
    const int q   = lane >> 3;
    const int r8  = lane & 7;
    const int arow_base = wm * 32 + r8 + (q & 1) * 8;
    const int acol_add  = (q >> 1) * 8;
    const int brow_base = wn * 32 + (q >> 1) * 8 + r8;
    const int bcol_add  = (q & 1) * 8;

    for (int r = 0; r < 17; r++) {
        __syncthreads();   // prev iter's scatter done before W overwrite

        // ---- load W_r tile: 64 rows x 128 bf16, hi+lo ----
#pragma unroll
        for (int t = 0; t < 2; t++) {
            const __nv_bfloat16* srcp =
                (t ? Wtlo : Wthi) + (size_t)r * 16384 + (size_t)nhalf * 64 * H_DIM;
            char* dstb = smem + (t ? SM_W_LO : SM_W_HI);
#pragma unroll
            for (int i = 0; i < 4; i++) {
                int idx = tid + i * 256;
                int row = idx >> 4;
                int c   = idx & 15;
                uint4 v = *(const uint4*)(srcp + (size_t)row * H_DIM + c * 8);
                *(uint4*)(dstb + row * PITCH + c * 16) = v;
            }
        }
        __syncthreads();

        float acc[2][4][4];
#pragma unroll
        for (int mt = 0; mt < 2; mt++)
#pragma unroll
            for (int nt = 0; nt < 4; nt++)
#pragma unroll
                for (int c = 0; c < 4; c++) acc[mt][nt][c] = 0.f;

#pragma unroll
        for (int ks = 0; ks < 8; ks++) {
            const int k0 = ks * 16;
            uint32_t ah[2][4], al[2][4], bh[4][2], bl[4][2];
#pragma unroll
            for (int mt = 0; mt < 2; mt++) {
                uint32_t off = (uint32_t)((arow_base + mt * 16) * PITCH
                                          + (k0 + acol_add) * 2);
                LDMX4(ah[mt][0], ah[mt][1], ah[mt][2], ah[mt][3], sb + SM_A_HI + off);
                LDMX4(al[mt][0], al[mt][1], al[mt][2], al[mt][3], sb + SM_A_LO + off);
            }
#pragma unroll
            for (int p = 0; p < 2; p++) {
                uint32_t off = (uint32_t)((brow_base + p * 16) * PITCH
                                          + (k0 + bcol_add) * 2);
                LDMX4(bh[2 * p][0], bh[2 * p][1], bh[2 * p + 1][0], bh[2 * p + 1][1],
                      sb + SM_W_HI + off);
                LDMX4(bl[2 * p][0], bl[2 * p][1], bl[2 * p + 1][0], bl[2 * p + 1][1],
                      sb + SM_W_LO + off);
            }
#pragma unroll
            for (int mt = 0; mt < 2; mt++)
#pragma unroll
                for (int nt = 0; nt < 4; nt++) {
                    MMA_BF16(acc[mt][nt], ah[mt], bh[nt]);
                    MMA_BF16(acc[mt][nt], ah[mt], bl[nt]);
                    MMA_BF16(acc[mt][nt], al[mt], bh[nt]);
                }
        }
        __syncthreads();   // all warps done reading W -> safe to overlay

        // ---- store acc tile to smem (128 rows x 64 cols) ----
        {
            const int r0 = wm * 32 + (lane >> 2);
            const int cB = wn * 32 + (lane & 3) * 2;
#pragma unroll
            for (int mt = 0; mt < 2; mt++) {
                int row = r0 + mt * 16;
#pragma unroll
                for (int nt = 0; nt < 4; nt++) {
                    int col = cB + nt * 8;
                    *(float2*)&stile[row * PITCHF + col] =
                        make_float2(acc[mt][nt][0], acc[mt][nt][1]);
                    *(float2*)&stile[(row + 8) * PITCHF + col] =
                        make_float2(acc[mt][nt][2], acc[mt][nt][3]);
                }
            }
        }
        __syncthreads();

        // ---- scatter ----
        const int c4 = (lane & 15) * 4;       // fp32 col within half (0..60)
        if (r < N_REL) {
            const int b     = r * NT + mtile;
            const int start = boff[b];
            const int n     = bcnt[b];
            for (int eb = wid * 2; eb < n; eb += 16) {
                int e = eb + (lane >> 4);
                if (e < n) {
                    uint32_t p = perm[start + e];
                    int sl = (int)(p & 127u);
                    int d  = (int)(p >> 7);
                    float4 v = *(const float4*)&stile[sl * PITCHF + c4];
                    float* o = OUT + (size_t)d * H_DIM + nhalf * 64 + c4;
                    RED_V4(o, v);
                }
            }
        } else {
            for (int rr = wid * 2; rr < 128; rr += 16) {
                int row = rr + (lane >> 4);
                int g   = m0 + row;
                if (g < M) {
                    float4 v = *(const float4*)&stile[row * PITCHF + c4];
                    float* o = OUT + (size_t)g * H_DIM + nhalf * 64 + c4;
                    RED_V4(o, v);
                }
            }
        }
    }
}

// ---------------------------------------------------------------------------
// Final ReLU.
// ---------------------------------------------------------------------------
__global__ void relu_kernel(float* __restrict__ x, int n4)
{
    int i = blockIdx.x * blockDim.x + threadIdx.x;
    if (i >= n4) return;
    float4 v = ((float4*)x)[i];
    v.x = fmaxf(v.x, 0.f); v.y = fmaxf(v.y, 0.f);
    v.z = fmaxf(v.z, 0.f); v.w = fmaxf(v.w, 0.f);
    ((float4*)x)[i] = v;
}

// ---------------------------------------------------------------------------
// Launch
// ---------------------------------------------------------------------------
extern "C" void kernel_launch(void* const* d_in, const int* in_sizes, int n_in,
                              void* d_out, int out_size)
{
    const float* entity_emb = (const float*)d_in[0];
    const float* basis1     = (const float*)d_in[1];
    const float* w_comp1    = (const float*)d_in[2];
    const float* loop_w1    = (const float*)d_in[3];
    const float* bias1      = (const float*)d_in[4];
    const float* basis2     = (const float*)d_in[5];
    const float* w_comp2    = (const float*)d_in[6];
    const float* loop_w2    = (const float*)d_in[7];
    const float* bias2      = (const float*)d_in[8];
    const int*   src        = (const int*)d_in[9];
    const int*   dst        = (const int*)d_in[10];
    const int*   rel        = (const int*)d_in[11];
    float*       out        = (float*)d_out;

    const int E = in_sizes[9];

    __nv_bfloat16 *dWth, *dWtl, *dAh, *dAl;
    float *dH1;
    int *dcnt, *doff, *dcur;
    uint32_t *dperm;
    cudaGetSymbolAddress((void**)&dWth,  g_Wt_hi);
    cudaGetSymbolAddress((void**)&dWtl,  g_Wt_lo);
    cudaGetSymbolAddress((void**)&dAh,   g_A_hi);
    cudaGetSymbolAddress((void**)&dAl,   g_A_lo);
    cudaGetSymbolAddress((void**)&dH1,   g_H1);
    cudaGetSymbolAddress((void**)&dcnt,  g_cnt);
    cudaGetSymbolAddress((void**)&doff,  g_off);
    cudaGetSymbolAddress((void**)&dcur,  g_cur);
    cudaGetSymbolAddress((void**)&dperm, g_perm);

    cudaFuncSetAttribute(gemm_scatter_kernel,
                         cudaFuncAttributeMaxDynamicSharedMemorySize, GEMM_SMEM);

    const int cb_total  = 17 * H_DIM * H_DIM;
    const int cb_blocks = (cb_total + 255) / 256;
    const int n4        = N_ENT * H_DIM / 4;
    const int sp_blocks = (n4 + 255) / 256;
    const int io_total  = N_ENT * H_DIM;
    const int io_blocks = (io_total + 255) / 256;
    const int eg_blocks = (E + 255) / 256;
    dim3 gemm_grid(2, NT);

    // ---------------- Edge binning (once per call) ----------------
    zero_cnt_kernel<<<(NBINS + 255) / 256, 256>>>(dcnt);
    hist_kernel<<<eg_blocks, 256>>>(src, rel, dcnt, E);
    scan_kernel<<<1, 1024>>>(dcnt, doff, dcur);
    fill_kernel<<<eg_blocks, 256>>>(src, dst, rel, dcur, dperm, E);

    // ---------------- Layer 1 ----------------
    combine_bases_kernel<<<cb_blocks, 256>>>(basis1, w_comp1, loop_w1, dWth, dWtl);
    split_kernel<<<sp_blocks, 256>>>(entity_emb, dAh, dAl, n4, 0);
    init_out_kernel<<<io_blocks, 256>>>(dH1, bias1, io_total);
    gemm_scatter_kernel<<<gemm_grid, 256, GEMM_SMEM>>>(dAh, dAl, dWth, dWtl,
                                                       doff, dcnt, dperm, dH1, N_ENT);

    // ---------------- Layer 2 ----------------
    combine_bases_kernel<<<cb_blocks, 256>>>(basis2, w_comp2, loop_w2, dWth, dWtl);
    split_kernel<<<sp_blocks, 256>>>(dH1, dAh, dAl, n4, 1);   // fused ReLU
    init_out_kernel<<<io_blocks, 256>>>(out, bias2, io_total);
    gemm_scatter_kernel<<<gemm_grid, 256, GEMM_SMEM>>>(dAh, dAl, dWth, dWtl,
                                                       doff, dcnt, dperm, out, N_ENT);
    relu_kernel<<<sp_blocks, 256>>>(out, n4);
}